// round 8
// baseline (speedup 1.0000x reference)
#include <cuda_runtime.h>
#include <cuda_bf16.h>
#include <math.h>

// DynamicRouter: logits = x @ W^T + b + 0.1*noise ; top-2 ; sparse softmax.
// x[B=8,S=4096,D=768] f32, W[E=8,D=768] f32, b[8] f32, noise[B,S,8] f32.
//
// R8: R7's cp.async 3-stage ring + expert-paired fma.rn.f32x2.
// W stored in smem as {W[2ep][d],W[2ep+1][d]} pairs; each x scalar duplicated
// into an f32x2; pacc[t][ep] accumulates both experts at once ->
// 64 FFMA2/chunk instead of 128 FFMA (FMA-pipe floor halves).

#define D_DIM        768
#define E_DIM        8
#define EPAIRS       (E_DIM / 2)              // 4
#define TOK_PER_WARP 4
#define WARPS        8
#define BLOCK        (WARPS * 32)
#define TOK_PER_BLK  (WARPS * TOK_PER_WARP)   // 32
#define D4           (D_DIM / 4)              // 192
#define NCHUNK       (D4 / 32)                // 6
#define NSTAGE       3
#define SWP_BYTES    (EPAIRS * D_DIM * 8)     // 24576 (u64 per (ep,d))
#define SX_WARP_F4   (NSTAGE * TOK_PER_WARP * 32)   // 384 float4 = 6 KB/warp
#define SMEM_BYTES   (SWP_BYTES + WARPS * SX_WARP_F4 * 16)  // 73728
#define NOISE_STD    0.1f

#define CP_ASYNC16(dst32, src) \
    asm volatile("cp.async.cg.shared.global [%0], [%1], 16;" \
                 :: "r"(dst32), "l"(src) : "memory")
#define CP_COMMIT() asm volatile("cp.async.commit_group;" ::: "memory")
#define CP_WAIT(n)  asm volatile("cp.async.wait_group %0;" :: "n"(n) : "memory")

// packed f32x2 FMA: acc = a*b + acc (both halves independently)
#define FMA_F32X2(acc, a, b) \
    asm("fma.rn.f32x2 %0, %1, %2, %0;" : "+l"(acc) : "l"(a), "l"(b))
// duplicate one f32 into both halves of a u64 (f32x2 {v,v})
#define DUP_F32X2(dst, v) \
    asm("mov.b64 %0, {%1, %1};" : "=l"(dst) : "f"(v))
#define UNPACK_F32X2(lo, hi, in) \
    asm("mov.b64 {%0, %1}, %2;" : "=f"(lo), "=f"(hi) : "l"(in))

__global__ __launch_bounds__(BLOCK, 3)
void router_kernel(const float* __restrict__ x,
                   const float* __restrict__ W,
                   const float* __restrict__ b,
                   const float* __restrict__ noise,
                   float* __restrict__ out,
                   int nTokens, int writeIdx)
{
    extern __shared__ char smem[];
    float2* sWp = reinterpret_cast<float2*>(smem);           // [EPAIRS*D_DIM] pairs
    float4* sX  = reinterpret_cast<float4*>(smem + SWP_BYTES); // ring [WARPS][NSTAGE][TOK*32]

    const int tid  = threadIdx.x;
    const int lane = tid & 31;
    const int wid  = tid >> 5;

    // Stage W into smem as expert pairs: sWp[ep*768+d] = {W[2ep][d], W[2ep+1][d]}
    for (int i = tid; i < EPAIRS * D_DIM; i += BLOCK) {
        const int ep = i / D_DIM;
        const int d  = i - ep * D_DIM;
        sWp[i] = make_float2(W[(2 * ep) * D_DIM + d], W[(2 * ep + 1) * D_DIM + d]);
    }
    __syncthreads();

    const int tokBase = blockIdx.x * TOK_PER_BLK + wid * TOK_PER_WARP;
    if (tokBase >= nTokens) return;

    const float4* x4 = reinterpret_cast<const float4*>(x) + (size_t)tokBase * D4;

    float4* myX = sX + wid * SX_WARP_F4;
    const unsigned myX32 = (unsigned)__cvta_generic_to_shared(myX);

    // pacc[t][ep] = f32x2 {logit_{2ep}, logit_{2ep+1}} per-lane partials
    unsigned long long pacc[TOK_PER_WARP][EPAIRS];
    #pragma unroll
    for (int t = 0; t < TOK_PER_WARP; t++)
        #pragma unroll
        for (int ep = 0; ep < EPAIRS; ep++) pacc[t][ep] = 0ull;

    auto issue = [&](int c, int s) {
        #pragma unroll
        for (int t = 0; t < TOK_PER_WARP; t++)
            CP_ASYNC16(myX32 + (unsigned)(((s * TOK_PER_WARP + t) * 32 + lane) * 16),
                       x4 + (size_t)t * D4 + c * 32 + lane);
        CP_COMMIT();
    };

    auto compute = [&](int c, int s) {
        // read back this lane's 4 x-packets (only bytes this lane wrote)
        float4 xv[TOK_PER_WARP];
        #pragma unroll
        for (int t = 0; t < TOK_PER_WARP; t++)
            xv[t] = myX[(s * TOK_PER_WARP + t) * 32 + lane];
        // duplicate each x scalar into an f32x2
        unsigned long long xx[TOK_PER_WARP][4];
        #pragma unroll
        for (int t = 0; t < TOK_PER_WARP; t++) {
            DUP_F32X2(xx[t][0], xv[t].x);
            DUP_F32X2(xx[t][1], xv[t].y);
            DUP_F32X2(xx[t][2], xv[t].z);
            DUP_F32X2(xx[t][3], xv[t].w);
        }
        const int p = c * 32 + lane;    // packet index; d-base = 4*p
        #pragma unroll
        for (int ep = 0; ep < EPAIRS; ep++) {
            // 4 consecutive u64 W-pairs for d = 4p..4p+3 -> two LDS.128
            const ulonglong2* w2 =
                reinterpret_cast<const ulonglong2*>(sWp + ep * D_DIM + 4 * p);
            const ulonglong2 wa = w2[0];
            const ulonglong2 wb = w2[1];
            #pragma unroll
            for (int t = 0; t < TOK_PER_WARP; t++) {
                FMA_F32X2(pacc[t][ep], xx[t][0], wa.x);
                FMA_F32X2(pacc[t][ep], xx[t][1], wa.y);
                FMA_F32X2(pacc[t][ep], xx[t][2], wb.x);
                FMA_F32X2(pacc[t][ep], xx[t][3], wb.y);
            }
        }
    };

    // fully unrolled 3-deep pipeline over 6 chunks
    issue(0, 0); issue(1, 1); issue(2, 2);           // pending: 3
    CP_WAIT(2); compute(0, 0); issue(3, 0);
    CP_WAIT(2); compute(1, 1); issue(4, 1);
    CP_WAIT(2); compute(2, 2); issue(5, 2);
    CP_WAIT(2); compute(3, 0);
    CP_WAIT(1); compute(4, 1);
    CP_WAIT(0); compute(5, 2);

    // Unpack into 32 scalars in v = t*8 + e order
    float acc[TOK_PER_WARP * E_DIM];
    #pragma unroll
    for (int t = 0; t < TOK_PER_WARP; t++)
        #pragma unroll
        for (int ep = 0; ep < EPAIRS; ep++) {
            float lo, hi;
            UNPACK_F32X2(lo, hi, pacc[t][ep]);
            acc[t * E_DIM + 2 * ep]     = lo;
            acc[t * E_DIM + 2 * ep + 1] = hi;
        }

    // Log-halving butterfly: after 5 steps lane l holds the complete 32-lane
    // sum for value index v == l  (v = t*8 + e).
    #pragma unroll
    for (int m = 16; m >= 1; m >>= 1) {
        const bool upper = (lane & m) != 0;
        #pragma unroll
        for (int i = 0; i < m; i++) {
            const float lo = acc[i], hi = acc[i + m];
            const float send = upper ? lo : hi;
            const float recv = __shfl_xor_sync(0xFFFFFFFFu, send, m);
            acc[i] = upper ? (hi + recv) : (lo + recv);
        }
    }
    const float sum = acc[0];

    const int t = lane >> 3;            // token within warp
    const int e = lane & 7;             // expert
    const long tok = (long)tokBase + t;

    const float logit = sum + __ldg(b + e)
                      + NOISE_STD * __ldg(noise + (size_t)tokBase * E_DIM + lane);

    // top-1 over the 8-lane expert group (ties -> lower index, jax top_k order)
    float v1 = logit; int i1 = e;
    #pragma unroll
    for (int off = 1; off < 8; off <<= 1) {
        const float ov = __shfl_xor_sync(0xFFFFFFFFu, v1, off);
        const int   oi = __shfl_xor_sync(0xFFFFFFFFu, i1, off);
        if (ov > v1 || (ov == v1 && oi < i1)) { v1 = ov; i1 = oi; }
    }
    // top-2: exclude winner, reduce again
    float v2 = (e == i1) ? -INFINITY : logit; int i2 = e;
    #pragma unroll
    for (int off = 1; off < 8; off <<= 1) {
        const float ov = __shfl_xor_sync(0xFFFFFFFFu, v2, off);
        const int   oi = __shfl_xor_sync(0xFFFFFFFFu, i2, off);
        if (ov > v2 || (ov == v2 && oi < i2)) { v2 = ov; i2 = oi; }
    }

    // 2-element softmax: p1 = 1/(1+exp(v2-v1)), p2 = exp(v2-v1)*p1  (arg <= 0)
    const float ed  = __expf(v2 - v1);
    const float inv = 1.0f / (1.0f + ed);
    const float p   = (e == i1) ? inv : ((e == i2) ? ed * inv : 0.0f);

    out[(size_t)tokBase * E_DIM + lane] = p;   // coalesced 128B per warp

    if (writeIdx && e == 0) {
        float* idxOut = out + (size_t)nTokens * E_DIM;
        idxOut[tok * 2 + 0] = (float)i1;
        idxOut[tok * 2 + 1] = (float)i2;
    }
}

extern "C" void kernel_launch(void* const* d_in, const int* in_sizes, int n_in,
                              void* d_out, int out_size)
{
    const float* x     = (const float*)d_in[0];
    const float* W     = (const float*)d_in[1];
    const float* b     = (const float*)d_in[2];
    const float* noise = (const float*)d_in[3];
    float* out = (float*)d_out;

    const int nTokens = in_sizes[3] / E_DIM;          // B*S from noise elem count
    const int writeIdx = (out_size >= nTokens * E_DIM + nTokens * 2) ? 1 : 0;

    // >48KB dynamic smem opt-in (unconditional; idempotent; capture-safe)
    cudaFuncSetAttribute(router_kernel,
                         cudaFuncAttributeMaxDynamicSharedMemorySize,
                         SMEM_BYTES);

    const int grid = (nTokens + TOK_PER_BLK - 1) / TOK_PER_BLK;
    router_kernel<<<grid, BLOCK, SMEM_BYTES>>>(x, W, b, noise, out, nTokens, writeIdx);
}